// round 3
// baseline (speedup 1.0000x reference)
#include <cuda_runtime.h>
#include <math.h>

#define Bsz 256
#define Hsz 512
#define Isz 512

// ---------------- scratch (device globals, no allocation) ----------------
__device__ float g_partial[4 * 4 * Bsz * Hsz]; // [z][gate][b][k] GEMM K-split partials (8 MB)
__device__ float g_hbp[4 * Bsz * Hsz];         // [z][b][k] hebb-dot h-split partials (2 MB)
__device__ float g_itc[Bsz * Hsz];             // inputstocell
__device__ float g_eta[Bsz];                   // tanh(hactiv @ Wmod.T + bmod)

// ---------------------------------------------------------------------------
// Fused kernel 1: gate GEMMs + hebb contraction, block-range dispatched.
// GEMM blocks (128): compute-bound register-tiled fp32 GEMM on x/h0 vs 7
//   weight matrices + plastic w.
// HEBBDOT blocks (512): stream hebb once (268 MB) computing per-sample
//   h2c partials. Pure DRAM stream.
// Interleaved 1:4 by blockIdx so both kinds coexist in every wave -> the
// FMA pipe (gemm) hides under the HBM stream (hebbdot).
// ---------------------------------------------------------------------------
#define N_GEMM 128          // 8(nx) x 4(ny) x 4(z)
#define N_HEBB 512          // 2(hz) x 256(b)
#define GRID_FUSED (N_GEMM + N_HEBB)

__global__ __launch_bounds__(256) void fused_gemm_hebbdot(
    const float* __restrict__ x, const float* __restrict__ h0,
    const float* __restrict__ Wxf, const float* __restrict__ Wxi,
    const float* __restrict__ Wxo, const float* __restrict__ Wxc,
    const float* __restrict__ Whf, const float* __restrict__ Whi,
    const float* __restrict__ Who, const float* __restrict__ w,
    const float* __restrict__ hebb)
{
    // union smem: gemm needs (2+8)*16*68 floats = 43520 B; hebbdot needs 1 KB
    __shared__ float smem[(2 + 8) * 16 * 68];

    const int bid = blockIdx.x;
    const int tid = threadIdx.x;

    // every 5th block (while gemm blocks remain) is a gemm block
    const bool is_gemm = (bid % 5 == 0) && (bid / 5 < N_GEMM);

    if (!is_gemm) {
        // ---------------- hebbdot path ----------------
        const int n_gemm_before = min((bid + 4) / 5, N_GEMM);
        const int hbid = bid - n_gemm_before;      // 0..511
        const int b = hbid >> 1;
        const int hz = hbid & 1;                   // 256-row half of h
        const int k4 = tid & 127;                  // float4 column
        const int hh = tid >> 7;                   // sub-slab (128 rows)

        float* sh = smem;                          // 256 floats
        sh[tid] = h0[b * Hsz + hz * 256 + tid];
        __syncthreads();

        const float4* hp = (const float4*)(hebb + (size_t)b * Hsz * Hsz
                                                + (size_t)(hz * 256 + hh * 128) * Hsz) + k4;
        float4 acc = {0.f, 0.f, 0.f, 0.f};
#pragma unroll 8
        for (int h = 0; h < 128; h++) {
            const float4 v = __ldcs(&hp[(size_t)h * 128]);
            const float s = sh[hh * 128 + h];
            acc.x += s * v.x; acc.y += s * v.y; acc.z += s * v.z; acc.w += s * v.w;
        }
        const int z = hz * 2 + hh;
        ((float4*)(g_hbp + (z * Bsz + b) * Hsz))[k4] = acc;
        return;
    }

    // ---------------- gemm path ----------------
    const int gid = bid / 5;                       // 0..127
    const int nx = gid & 7;                        // 8
    const int ny = (gid >> 3) & 3;                 // 4
    const int z  = gid >> 5;                       // 4

    float (*sA)[16][68] = (float (*)[16][68])smem;              // [2][16][68]
    float (*sB)[16][68] = (float (*)[16][68])(smem + 2 * 16 * 68); // [8][16][68]

    const int m0 = ny * 64;
    const int n0 = nx * 64;
    const int kbase = z * 128;
    const int ty = tid >> 4, tx = tid & 15;

    float acc[4][16];
#pragma unroll
    for (int g = 0; g < 4; g++)
#pragma unroll
        for (int i = 0; i < 16; i++) acc[g][i] = 0.f;

    const float* Wt[7] = {Wxf, Wxi, Wxo, Wxc, Whf, Whi, Who};

    for (int kc = 0; kc < 128; kc += 16) {
        const int kk0 = kbase + kc;
        const int lk = tid & 15, lr = tid >> 4;
#pragma unroll
        for (int i = 0; i < 4; i++) {
            int m = lr + i * 16;
            sA[0][lk][m] = x[(m0 + m) * Isz + kk0 + lk];
            sA[1][lk][m] = h0[(m0 + m) * Hsz + kk0 + lk];
        }
#pragma unroll
        for (int j = 0; j < 7; j++) {
            const float* Wp = Wt[j];
#pragma unroll
            for (int i = 0; i < 4; i++) {
                int n = lr + i * 16;
                sB[j][lk][n] = Wp[(n0 + n) * Hsz + kk0 + lk]; // I==H==512 stride
            }
        }
        {
            const int ln = tid & 63, lz = tid >> 6;
#pragma unroll
            for (int i = 0; i < 4; i++) {
                int kk = lz + i * 4;
                sB[7][kk][ln] = w[(kk0 + kk) * Hsz + n0 + ln]; // w accessed [h][k]
            }
        }
        __syncthreads();

#pragma unroll
        for (int kk = 0; kk < 16; kk++) {
            const float4 ax4 = *(const float4*)&sA[0][kk][ty * 4];
            const float4 ah4 = *(const float4*)&sA[1][kk][ty * 4];
            const float ax[4] = {ax4.x, ax4.y, ax4.z, ax4.w};
            const float ah[4] = {ah4.x, ah4.y, ah4.z, ah4.w};
#pragma unroll
            for (int g = 0; g < 4; g++) {
                const float4 bx4 = *(const float4*)&sB[g][kk][tx * 4];
                const float4 bh4 = *(const float4*)&sB[(g < 3) ? (4 + g) : 7][kk][tx * 4];
                const float bx[4] = {bx4.x, bx4.y, bx4.z, bx4.w};
                const float bh[4] = {bh4.x, bh4.y, bh4.z, bh4.w};
#pragma unroll
                for (int mi = 0; mi < 4; mi++)
#pragma unroll
                    for (int ni = 0; ni < 4; ni++)
                        acc[g][mi * 4 + ni] += ax[mi] * bx[ni] + ah[mi] * bh[ni];
            }
        }
        __syncthreads();
    }

#pragma unroll
    for (int g = 0; g < 4; g++)
#pragma unroll
        for (int mi = 0; mi < 4; mi++) {
            int m = m0 + ty * 4 + mi, n = n0 + tx * 4;
            float4 v = {acc[g][mi * 4 + 0], acc[g][mi * 4 + 1],
                        acc[g][mi * 4 + 2], acc[g][mi * 4 + 3]};
            *(float4*)&g_partial[(((z * 4 + g) * Bsz) + m) * Hsz + n] = v;
        }
}

// ---------------------------------------------------------------------------
// Kernel 2: combine partials, gate nonlinearities, cell/hactiv outputs,
// inputstocell scratch, and block-wide reduction for the neuromodulator eta.
// grid 256 (one block per batch row), 512 threads (one per k).
// ---------------------------------------------------------------------------
__global__ __launch_bounds__(512) void combine(
    const float* __restrict__ c0, const float* __restrict__ alpha,
    const float* __restrict__ bxf, const float* __restrict__ bhf,
    const float* __restrict__ bxi, const float* __restrict__ bhi,
    const float* __restrict__ bxo, const float* __restrict__ bho,
    const float* __restrict__ bxc,
    const float* __restrict__ Wmod, const float* __restrict__ bmod,
    float* __restrict__ out_h, float* __restrict__ out_c)
{
    const int b = blockIdx.x, k = threadIdx.x;

    float p[4];
#pragma unroll
    for (int g = 0; g < 4; g++) {
        float s = 0.f;
#pragma unroll
        for (int z = 0; z < 4; z++) s += g_partial[(((z * 4 + g) * Bsz) + b) * Hsz + k];
        p[g] = s;
    }
    float hbs = 0.f;
#pragma unroll
    for (int z = 0; z < 4; z++) hbs += g_hbp[(z * Bsz + b) * Hsz + k];

    const float fgt = 1.f / (1.f + expf(-(p[0] + bxf[k] + bhf[k])));
    const float ipt = 1.f / (1.f + expf(-(p[1] + bxi[k] + bhi[k])));
    const float opt = 1.f / (1.f + expf(-(p[2] + bxo[k] + bho[k])));
    const float itc = tanhf(p[3] + bxc[k] + alpha[k] * hbs);
    const float cell = fgt * c0[b * Hsz + k] + ipt * itc;
    const float hact = opt * tanhf(cell);

    out_h[b * Hsz + k] = hact;
    out_c[b * Hsz + k] = cell;
    g_itc[b * Hsz + k] = itc;

    // eta[b] = tanh( sum_k hact*Wmod[k] + bmod )
    float v = hact * Wmod[k];
#pragma unroll
    for (int off = 16; off; off >>= 1) v += __shfl_xor_sync(0xffffffffu, v, off);
    __shared__ float sred[16];
    const int lane = k & 31, wid = k >> 5;
    if (lane == 0) sred[wid] = v;
    __syncthreads();
    if (wid == 0) {
        float t = (lane < 16) ? sred[lane] : 0.f;
#pragma unroll
        for (int off = 8; off; off >>= 1) t += __shfl_xor_sync(0xffffffffu, t, off);
        if (lane == 0) g_eta[b] = tanhf(t + bmod[0]);
    }
}

// ---------------------------------------------------------------------------
// Kernel 3: Hebbian trace update (dominant memory cost: 268 MB read + 268 MB write).
//   hebb_new[b,h,k] = clip(hebb[b,h,k] + (eta[b]*Wfan[k]+bfan[k])*itc[b,k] * h0[b,h], +-2)
// grid (16, 256): 32 h-rows per block, 128 threads x float4 over k.
// Streaming cache hints: the 536 MB hebb stream has zero reuse.
// ---------------------------------------------------------------------------
__global__ __launch_bounds__(128) void hebbupd(
    const float* __restrict__ h0, const float* __restrict__ hebb,
    const float* __restrict__ Wfan, const float* __restrict__ bfan,
    float* __restrict__ out_hebb)
{
    const int b = blockIdx.y, hb0 = blockIdx.x * 32, t = threadIdx.x;
    __shared__ float4 s[128];
    __shared__ float sh0[32];

    const float eta = g_eta[b];
    {
        const int k = t * 4;
        const float4 it = *(const float4*)&g_itc[b * Hsz + k];
        float4 sv;
        sv.x = (eta * Wfan[k + 0] + bfan[k + 0]) * it.x;
        sv.y = (eta * Wfan[k + 1] + bfan[k + 1]) * it.y;
        sv.z = (eta * Wfan[k + 2] + bfan[k + 2]) * it.z;
        sv.w = (eta * Wfan[k + 3] + bfan[k + 3]) * it.w;
        s[t] = sv;
    }
    if (t < 32) sh0[t] = h0[b * Hsz + hb0 + t];
    __syncthreads();

    const float4 sk = s[t];
    const float4* hp = (const float4*)(hebb + (size_t)b * Hsz * Hsz + (size_t)hb0 * Hsz) + t;
    float4* op = (float4*)(out_hebb + (size_t)b * Hsz * Hsz + (size_t)hb0 * Hsz) + t;
#pragma unroll 8
    for (int hh = 0; hh < 32; hh++) {
        float4 v = __ldcs(&hp[(size_t)hh * 128]);
        const float hv = sh0[hh];
        v.x = fminf(fmaxf(v.x + hv * sk.x, -2.f), 2.f);
        v.y = fminf(fmaxf(v.y + hv * sk.y, -2.f), 2.f);
        v.z = fminf(fmaxf(v.z + hv * sk.z, -2.f), 2.f);
        v.w = fminf(fmaxf(v.w + hv * sk.w, -2.f), 2.f);
        __stcs(&op[(size_t)hh * 128], v);
    }
}

// ---------------------------------------------------------------------------
extern "C" void kernel_launch(void* const* d_in, const int* in_sizes, int n_in,
                              void* d_out, int out_size)
{
    const float* x     = (const float*)d_in[0];
    const float* h0    = (const float*)d_in[1];
    const float* c0    = (const float*)d_in[2];
    const float* hebb  = (const float*)d_in[3];
    const float* w     = (const float*)d_in[4];
    const float* alpha = (const float*)d_in[5];
    const float* Wxf   = (const float*)d_in[6];
    const float* bxf   = (const float*)d_in[7];
    const float* Whf   = (const float*)d_in[8];
    const float* bhf   = (const float*)d_in[9];
    const float* Wxi   = (const float*)d_in[10];
    const float* bxi   = (const float*)d_in[11];
    const float* Whi   = (const float*)d_in[12];
    const float* bhi   = (const float*)d_in[13];
    const float* Wxo   = (const float*)d_in[14];
    const float* bxo   = (const float*)d_in[15];
    const float* Who   = (const float*)d_in[16];
    const float* bho   = (const float*)d_in[17];
    const float* Wxc   = (const float*)d_in[18];
    const float* bxc   = (const float*)d_in[19];
    const float* Wmod  = (const float*)d_in[20];
    const float* bmod  = (const float*)d_in[21];
    const float* Wfan  = (const float*)d_in[22];
    const float* bfan  = (const float*)d_in[23];

    float* out = (float*)d_out;
    float* out_h    = out;                     // hactiv [256,512]
    float* out_c    = out + Bsz * Hsz;         // cell   [256,512]
    float* out_hebb = out + 2 * Bsz * Hsz;     // hebb_new [256,512,512]

    fused_gemm_hebbdot<<<GRID_FUSED, 256>>>(x, h0, Wxf, Wxi, Wxo, Wxc,
                                            Whf, Whi, Who, w, hebb);
    combine<<<256, 512>>>(c0, alpha, bxf, bhf, bxi, bhi, bxo, bho, bxc, Wmod, bmod,
                          out_h, out_c);
    hebbupd<<<dim3(16, 256), 128>>>(h0, hebb, Wfan, bfan, out_hebb);
}

// round 7
// speedup vs baseline: 1.2354x; 1.2354x over previous
#include <cuda_runtime.h>
#include <math.h>

#define Bsz 256
#define Hsz 512
#define Isz 512

// ---------------- scratch (device globals, no allocation) ----------------
__device__ float g_partial[4 * 4 * Bsz * Hsz]; // [z][gate][b][k] GEMM K-split partials (8 MB)
__device__ float g_hbp[4 * Bsz * Hsz];         // [z][b][k] hebb-dot h-split partials (2 MB)
__device__ float g_itc[Bsz * Hsz];             // inputstocell
__device__ float g_eta[Bsz];                   // tanh(hactiv @ Wmod.T + bmod)

// ---------------------------------------------------------------------------
// Fused kernel 1: gate GEMMs + hebb contraction, block-range dispatched.
//
// GEMM blocks (512): ONE gate per block (64x64 tile, 128-k slab):
//   out[g] partial = x·Wx[g] + h0·Wh[g]   (g=3 uses plastic w as Wh)
//   Only 16 accumulators/thread -> ~55 regs -> 4 blocks/SM possible.
// HEBBDOT blocks (512): stream hebb once (268 MB), per-sample h2c partials.
//
// Interleaved 1:1 so each SM carries both a DRAM stream and FMA work.
// __launch_bounds__(256,4) caps regs at 64 -> occupancy 50%.
// ---------------------------------------------------------------------------
#define N_GEMM 512
#define N_HEBB 512
#define GRID_FUSED (N_GEMM + N_HEBB)

__global__ __launch_bounds__(256, 4) void fused_gemm_hebbdot(
    const float* __restrict__ x, const float* __restrict__ h0,
    const float* __restrict__ Wxf, const float* __restrict__ Wxi,
    const float* __restrict__ Wxo, const float* __restrict__ Wxc,
    const float* __restrict__ Whf, const float* __restrict__ Whi,
    const float* __restrict__ Who, const float* __restrict__ w,
    const float* __restrict__ hebb)
{
    // union smem: gemm needs 4*16*68 floats = 17408 B; hebbdot needs 1 KB
    __shared__ float smem[4 * 16 * 68];

    const int bid = blockIdx.x;
    const int tid = threadIdx.x;

    if (bid & 1) {
        // ---------------- hebbdot path (odd blocks) ----------------
        const int hid = bid >> 1;                  // 0..511
        const int b = hid >> 1;
        const int hz = hid & 1;                    // 256-row half of h
        const int k4 = tid & 127;                  // float4 column
        const int hh = tid >> 7;                   // sub-slab (128 rows)

        float* sh = smem;                          // 256 floats
        sh[tid] = h0[b * Hsz + hz * 256 + tid];
        __syncthreads();

        const float4* hp = (const float4*)(hebb + (size_t)b * Hsz * Hsz
                                                + (size_t)(hz * 256 + hh * 128) * Hsz) + k4;
        float4 acc = {0.f, 0.f, 0.f, 0.f};
#pragma unroll 8
        for (int h = 0; h < 128; h++) {
            const float4 v = __ldcs(&hp[(size_t)h * 128]);
            const float s = sh[hh * 128 + h];
            acc.x += s * v.x; acc.y += s * v.y; acc.z += s * v.z; acc.w += s * v.w;
        }
        const int z = hz * 2 + hh;
        ((float4*)(g_hbp + (z * Bsz + b) * Hsz))[k4] = acc;
        return;
    }

    // ---------------- gemm path (even blocks) ----------------
    const int gid = bid >> 1;                      // 0..511
    const int g  = gid & 3;                        // gate
    const int nx = (gid >> 2) & 7;                 // 8 n-tiles
    const int ny = (gid >> 5) & 3;                 // 4 m-tiles
    const int z  = gid >> 7;                       // 4 k-slabs

    float (*sA)[68] = (float (*)[68])smem;                 // [2*16][68]: x rows 0-15, h rows 16-31
    float (*sB)[68] = (float (*)[68])(smem + 2 * 16 * 68); // [2*16][68]: Wx rows, Wh rows

    const int m0 = ny * 64;
    const int n0 = nx * 64;
    const int kbase = z * 128;
    const int ty = tid >> 4, tx = tid & 15;

    float acc[16];
#pragma unroll
    for (int i = 0; i < 16; i++) acc[i] = 0.f;

    const float* Wx = (g == 0) ? Wxf : (g == 1) ? Wxi : (g == 2) ? Wxo : Wxc;
    const float* Wh = (g == 0) ? Whf : (g == 1) ? Whi : (g == 2) ? Who : w;

    const int lk = tid & 15, lr = tid >> 4;

    for (int kc = 0; kc < 128; kc += 16) {
        const int kk0 = kbase + kc;
#pragma unroll
        for (int i = 0; i < 4; i++) {
            int m = lr + i * 16;
            sA[lk][m]      = x[(m0 + m) * Isz + kk0 + lk];
            sA[16 + lk][m] = h0[(m0 + m) * Hsz + kk0 + lk];
            int n = lr + i * 16;
            sB[lk][n] = Wx[(n0 + n) * Hsz + kk0 + lk];
        }
        if (g < 3) {
#pragma unroll
            for (int i = 0; i < 4; i++) {
                int n = lr + i * 16;
                sB[16 + lk][n] = Wh[(n0 + n) * Hsz + kk0 + lk];
            }
        } else {
            // plastic w accessed transposed: B[kk][n] = w[kk0+kk][n0+n]
            const int ln = tid & 63, lz = tid >> 6;
#pragma unroll
            for (int i = 0; i < 4; i++) {
                int kk = lz + i * 4;
                sB[16 + kk][ln] = Wh[(kk0 + kk) * Hsz + n0 + ln];
            }
        }
        __syncthreads();

#pragma unroll
        for (int kk = 0; kk < 16; kk++) {
            const float4 ax4 = *(const float4*)&sA[kk][ty * 4];
            const float4 ah4 = *(const float4*)&sA[16 + kk][ty * 4];
            const float4 bx4 = *(const float4*)&sB[kk][tx * 4];
            const float4 bh4 = *(const float4*)&sB[16 + kk][tx * 4];
            const float ax[4] = {ax4.x, ax4.y, ax4.z, ax4.w};
            const float ah[4] = {ah4.x, ah4.y, ah4.z, ah4.w};
            const float bx[4] = {bx4.x, bx4.y, bx4.z, bx4.w};
            const float bh[4] = {bh4.x, bh4.y, bh4.z, bh4.w};
#pragma unroll
            for (int mi = 0; mi < 4; mi++)
#pragma unroll
                for (int ni = 0; ni < 4; ni++)
                    acc[mi * 4 + ni] += ax[mi] * bx[ni] + ah[mi] * bh[ni];
        }
        __syncthreads();
    }

#pragma unroll
    for (int mi = 0; mi < 4; mi++) {
        int m = m0 + ty * 4 + mi, n = n0 + tx * 4;
        float4 v = {acc[mi * 4 + 0], acc[mi * 4 + 1], acc[mi * 4 + 2], acc[mi * 4 + 3]};
        *(float4*)&g_partial[(((z * 4 + g) * Bsz) + m) * Hsz + n] = v;
    }
}

// ---------------------------------------------------------------------------
// Kernel 2: combine partials, gate nonlinearities, cell/hactiv outputs,
// inputstocell scratch, and block-wide reduction for the neuromodulator eta.
// grid 256 (one block per batch row), 512 threads (one per k).
// ---------------------------------------------------------------------------
__global__ __launch_bounds__(512) void combine(
    const float* __restrict__ c0, const float* __restrict__ alpha,
    const float* __restrict__ bxf, const float* __restrict__ bhf,
    const float* __restrict__ bxi, const float* __restrict__ bhi,
    const float* __restrict__ bxo, const float* __restrict__ bho,
    const float* __restrict__ bxc,
    const float* __restrict__ Wmod, const float* __restrict__ bmod,
    float* __restrict__ out_h, float* __restrict__ out_c)
{
    const int b = blockIdx.x, k = threadIdx.x;

    float p[4];
#pragma unroll
    for (int g = 0; g < 4; g++) {
        float s = 0.f;
#pragma unroll
        for (int z = 0; z < 4; z++) s += g_partial[(((z * 4 + g) * Bsz) + b) * Hsz + k];
        p[g] = s;
    }
    float hbs = 0.f;
#pragma unroll
    for (int z = 0; z < 4; z++) hbs += g_hbp[(z * Bsz + b) * Hsz + k];

    const float fgt = 1.f / (1.f + expf(-(p[0] + bxf[k] + bhf[k])));
    const float ipt = 1.f / (1.f + expf(-(p[1] + bxi[k] + bhi[k])));
    const float opt = 1.f / (1.f + expf(-(p[2] + bxo[k] + bho[k])));
    const float itc = tanhf(p[3] + bxc[k] + alpha[k] * hbs);
    const float cell = fgt * c0[b * Hsz + k] + ipt * itc;
    const float hact = opt * tanhf(cell);

    out_h[b * Hsz + k] = hact;
    out_c[b * Hsz + k] = cell;
    g_itc[b * Hsz + k] = itc;

    // eta[b] = tanh( sum_k hact*Wmod[k] + bmod )
    float v = hact * Wmod[k];
#pragma unroll
    for (int off = 16; off; off >>= 1) v += __shfl_xor_sync(0xffffffffu, v, off);
    __shared__ float sred[16];
    const int lane = k & 31, wid = k >> 5;
    if (lane == 0) sred[wid] = v;
    __syncthreads();
    if (wid == 0) {
        float t = (lane < 16) ? sred[lane] : 0.f;
#pragma unroll
        for (int off = 8; off; off >>= 1) t += __shfl_xor_sync(0xffffffffu, t, off);
        if (lane == 0) g_eta[b] = tanhf(t + bmod[0]);
    }
}

// ---------------------------------------------------------------------------
// Kernel 3: Hebbian trace update (268 MB read + 268 MB write, pure stream).
//   hebb_new[b,h,k] = clip(hebb[b,h,k] + (eta[b]*Wfan[k]+bfan[k])*itc[b,k] * h0[b,h], +-2)
// grid (16, 256): 32 h-rows per block, 128 threads x float4 over k.
// ---------------------------------------------------------------------------
__global__ __launch_bounds__(128) void hebbupd(
    const float* __restrict__ h0, const float* __restrict__ hebb,
    const float* __restrict__ Wfan, const float* __restrict__ bfan,
    float* __restrict__ out_hebb)
{
    const int b = blockIdx.y, hb0 = blockIdx.x * 32, t = threadIdx.x;
    __shared__ float4 s[128];
    __shared__ float sh0[32];

    const float eta = g_eta[b];
    {
        const int k = t * 4;
        const float4 it = *(const float4*)&g_itc[b * Hsz + k];
        float4 sv;
        sv.x = (eta * Wfan[k + 0] + bfan[k + 0]) * it.x;
        sv.y = (eta * Wfan[k + 1] + bfan[k + 1]) * it.y;
        sv.z = (eta * Wfan[k + 2] + bfan[k + 2]) * it.z;
        sv.w = (eta * Wfan[k + 3] + bfan[k + 3]) * it.w;
        s[t] = sv;
    }
    if (t < 32) sh0[t] = h0[b * Hsz + hb0 + t];
    __syncthreads();

    const float4 sk = s[t];
    const float4* hp = (const float4*)(hebb + (size_t)b * Hsz * Hsz + (size_t)hb0 * Hsz) + t;
    float4* op = (float4*)(out_hebb + (size_t)b * Hsz * Hsz + (size_t)hb0 * Hsz) + t;
#pragma unroll 8
    for (int hh = 0; hh < 32; hh++) {
        float4 v = __ldcs(&hp[(size_t)hh * 128]);
        const float hv = sh0[hh];
        v.x = fminf(fmaxf(v.x + hv * sk.x, -2.f), 2.f);
        v.y = fminf(fmaxf(v.y + hv * sk.y, -2.f), 2.f);
        v.z = fminf(fmaxf(v.z + hv * sk.z, -2.f), 2.f);
        v.w = fminf(fmaxf(v.w + hv * sk.w, -2.f), 2.f);
        __stcs(&op[(size_t)hh * 128], v);
    }
}

// ---------------------------------------------------------------------------
extern "C" void kernel_launch(void* const* d_in, const int* in_sizes, int n_in,
                              void* d_out, int out_size)
{
    const float* x     = (const float*)d_in[0];
    const float* h0    = (const float*)d_in[1];
    const float* c0    = (const float*)d_in[2];
    const float* hebb  = (const float*)d_in[3];
    const float* w     = (const float*)d_in[4];
    const float* alpha = (const float*)d_in[5];
    const float* Wxf   = (const float*)d_in[6];
    const float* bxf   = (const float*)d_in[7];
    const float* Whf   = (const float*)d_in[8];
    const float* bhf   = (const float*)d_in[9];
    const float* Wxi   = (const float*)d_in[10];
    const float* bxi   = (const float*)d_in[11];
    const float* Whi   = (const float*)d_in[12];
    const float* bhi   = (const float*)d_in[13];
    const float* Wxo   = (const float*)d_in[14];
    const float* bxo   = (const float*)d_in[15];
    const float* Who   = (const float*)d_in[16];
    const float* bho   = (const float*)d_in[17];
    const float* Wxc   = (const float*)d_in[18];
    const float* bxc   = (const float*)d_in[19];
    const float* Wmod  = (const float*)d_in[20];
    const float* bmod  = (const float*)d_in[21];
    const float* Wfan  = (const float*)d_in[22];
    const float* bfan  = (const float*)d_in[23];

    float* out = (float*)d_out;
    float* out_h    = out;                     // hactiv [256,512]
    float* out_c    = out + Bsz * Hsz;         // cell   [256,512]
    float* out_hebb = out + 2 * Bsz * Hsz;     // hebb_new [256,512,512]

    fused_gemm_hebbdot<<<GRID_FUSED, 256>>>(x, h0, Wxf, Wxi, Wxo, Wxc,
                                            Whf, Whi, Who, w, hebb);
    combine<<<256, 512>>>(c0, alpha, bxf, bhf, bxi, bhi, bxo, bho, bxc, Wmod, bmod,
                          out_h, out_c);
    hebbupd<<<dim3(16, 256), 128>>>(h0, hebb, Wfan, bfan, out_hebb);
}